// round 1
// baseline (speedup 1.0000x reference)
#include <cuda_runtime.h>
#include <cstdint>

#define NN 50000
#define NE 400000
#define FULLM 0xffffffffu

// Scratch: per-node accumulator [NN,64] and edge count [NN].
__device__ float g_sum[NN * 64];
__device__ int   g_cnt[NN];

// ---------------------------------------------------------------------------
// Kernel 0: zero scratch
// ---------------------------------------------------------------------------
__global__ void __launch_bounds__(256) zero_k() {
    int tid = blockIdx.x * blockDim.x + threadIdx.x;
    int stride = gridDim.x * blockDim.x;
    for (int i = tid; i < NN * 64; i += stride) g_sum[i] = 0.0f;
    for (int i = tid; i < NN; i += stride) g_cnt[i] = 0;
}

// ---------------------------------------------------------------------------
// Kernel 1: edge kernel.
//   - whole 64KB filter bank cached in dynamic SMEM per CTA
//   - each lane preprocesses one edge; valid edges compacted via ballot
//   - warp sweeps valid edges: 8 corners x 4 in-ch x 2 out-ch per lane
//   - scatter via red.global.add.v4.f32 (16 lanes x 16B = 256B coalesced)
// ---------------------------------------------------------------------------
__global__ void __launch_bounds__(256) edge_k(const float* __restrict__ x,
                                              const int* __restrict__ ei,
                                              const float* __restrict__ filters) {
    extern __shared__ float sf[];  // 16384 floats = 64KB
    for (int i = threadIdx.x; i < 4096; i += blockDim.x)
        ((float4*)sf)[i] = ((const float4*)filters)[i];
    __syncthreads();

    const int lane = threadIdx.x & 31;
    const int gw = (blockIdx.x * blockDim.x + threadIdx.x) >> 5;
    const int nw = (gridDim.x * blockDim.x) >> 5;
    const int* __restrict__ rowp = ei;
    const int* __restrict__ colp = ei + NE;

    for (int base = gw * 32; base < NE; base += nw * 32) {
        const int e = base + lane;
        int row = 0;
        float fe0 = 0.f, fe1 = 0.f, fe2 = 0.f, fe3 = 0.f;
        float wcor[8];
        int off[8];
        bool valid = false;

        if (e < NE) {
            row = rowp[e];
            const int col = colp[e];
            atomicAdd(&g_cnt[row], 1);  // count ALL edges (reference semantics)
            const float* xr = x + row * 7;
            const float* xc = x + col * 7;
            fe0 = xc[0]; fe1 = xc[1]; fe2 = xc[2]; fe3 = xc[6];
            const float rx = fe0 - xr[0];
            const float ry = fe1 - xr[1];
            const float rz = fe2 - xr[2];
            const float d2 = rx * rx + ry * ry + rz * rz;
            if (d2 < 0.25f) {
                valid = true;
                const float t = 1.0f - 4.0f * d2;
                const float win = t * t * t;
                const float nrm = sqrtf(d2);
                const float s = tanhf(nrm) / (nrm + 1e-8f);
                // note axis reversal: a<-z, b<-y, c<-x
                const float a = (rz * s + 1.0f) * 1.5f;
                const float b = (ry * s + 1.0f) * 1.5f;
                const float c = (rx * s + 1.0f) * 1.5f;
                const float af = floorf(a), bf = floorf(b), cf = floorf(c);
                const int a0 = (int)af, b0 = (int)bf, c0 = (int)cf;
                const float ad = a - af, bd = b - bf, cd = c - cf;
                const int ia[2] = {a0, min(a0 + 1, 3)};
                const int ib[2] = {b0, min(b0 + 1, 3)};
                const int ic[2] = {c0, min(c0 + 1, 3)};
                const float wa[2] = {1.0f - ad, ad};
                const float wb[2] = {1.0f - bd, bd};
                const float wcc[2] = {1.0f - cd, cd};
#pragma unroll
                for (int ka = 0; ka < 2; ka++)
#pragma unroll
                    for (int kb = 0; kb < 2; kb++)
#pragma unroll
                        for (int kc = 0; kc < 2; kc++) {
                            const int k = (ka << 2) | (kb << 1) | kc;
                            off[k] = (((ia[ka] << 2) + ib[kb]) * 4 + ic[kc]) << 8;
                            wcor[k] = win * wa[ka] * wb[kb] * wcc[kc];
                        }
            }
        }

        unsigned vm = __ballot_sync(FULLM, valid);
        while (vm) {
            const int j = __ffs(vm) - 1;
            vm &= vm - 1;
            const int rj = __shfl_sync(FULLM, row, j);
            const float e0 = __shfl_sync(FULLM, fe0, j);
            const float e1 = __shfl_sync(FULLM, fe1, j);
            const float e2 = __shfl_sync(FULLM, fe2, j);
            const float e3 = __shfl_sync(FULLM, fe3, j);
            float acc0 = 0.f, acc1 = 0.f;
#pragma unroll
            for (int k = 0; k < 8; k++) {
                const float wk = __shfl_sync(FULLM, wcor[k], j);
                const int ok = __shfl_sync(FULLM, off[k], j);
                const float w0 = wk * e0, w1 = wk * e1, w2 = wk * e2, w3 = wk * e3;
                const float2* fp = (const float2*)(sf + ok) + lane;
                float2 q;
                q = fp[0];  acc0 += w0 * q.x; acc1 += w0 * q.y;
                q = fp[32]; acc0 += w1 * q.x; acc1 += w1 * q.y;
                q = fp[64]; acc0 += w2 * q.x; acc1 += w2 * q.y;
                q = fp[96]; acc0 += w3 * q.x; acc1 += w3 * q.y;
            }
            // pack 2ch/lane -> 4ch on lanes 0..15 for vectorized reduction
            const int src = (lane << 1) & 31;
            const float v0 = __shfl_sync(FULLM, acc0, src);
            const float v1 = __shfl_sync(FULLM, acc1, src);
            const float v2 = __shfl_sync(FULLM, acc0, src | 1);
            const float v3 = __shfl_sync(FULLM, acc1, src | 1);
            if (lane < 16) {
                float* dst = g_sum + (size_t)rj * 64 + (lane << 2);
                asm volatile("red.global.add.v4.f32 [%0], {%1,%2,%3,%4};"
                             :: "l"(dst), "f"(v0), "f"(v1), "f"(v2), "f"(v3)
                             : "memory");
            }
        }
    }
}

// ---------------------------------------------------------------------------
// Kernel 2: node epilogue — h=tanh(sum/cnt), concat, layernorm(68), W_out+b.
// One warp per node; lane covers channels {lane, lane+32, lane+64(<4)}.
// ---------------------------------------------------------------------------
__global__ void __launch_bounds__(256) node_k(const float* __restrict__ x,
                                              const float* __restrict__ gamma,
                                              const float* __restrict__ beta,
                                              const float* __restrict__ W,
                                              const float* __restrict__ bo,
                                              float* __restrict__ out) {
    const int lane = threadIdx.x & 31;
    const int n = (blockIdx.x * blockDim.x + threadIdx.x) >> 5;
    if (n >= NN) return;

    const float inv = 1.0f / (float)max(g_cnt[n], 1);
    const float* s = g_sum + (size_t)n * 64;

    float v0, v1, v2 = 0.f;
    if (lane < 4) {
        v0 = (lane < 3) ? x[n * 7 + lane] : x[n * 7 + 6];
        v2 = tanhf(s[lane + 60] * inv);
    } else {
        v0 = tanhf(s[lane - 4] * inv);
    }
    v1 = tanhf(s[lane + 28] * inv);

    float total = v0 + v1 + v2;
#pragma unroll
    for (int o = 16; o; o >>= 1) total += __shfl_xor_sync(FULLM, total, o);
    const float mean = total * (1.0f / 68.0f);

    const float d0 = v0 - mean;
    const float d1 = v1 - mean;
    const float d2v = (lane < 4) ? (v2 - mean) : 0.f;
    float sq = d0 * d0 + d1 * d1 + d2v * d2v;
#pragma unroll
    for (int o = 16; o; o >>= 1) sq += __shfl_xor_sync(FULLM, sq, o);
    const float rstd = rsqrtf(sq * (1.0f / 68.0f) + 1e-5f);

    const int c0 = lane, c1 = lane + 32, c2 = lane + 64;
    const float n0 = d0 * rstd * gamma[c0] + beta[c0];
    const float n1 = d1 * rstd * gamma[c1] + beta[c1];
    float p0 = n0 * W[c0 * 3 + 0] + n1 * W[c1 * 3 + 0];
    float p1 = n0 * W[c0 * 3 + 1] + n1 * W[c1 * 3 + 1];
    float p2 = n0 * W[c0 * 3 + 2] + n1 * W[c1 * 3 + 2];
    if (lane < 4) {
        const float n2 = d2v * rstd * gamma[c2] + beta[c2];
        p0 += n2 * W[c2 * 3 + 0];
        p1 += n2 * W[c2 * 3 + 1];
        p2 += n2 * W[c2 * 3 + 2];
    }
#pragma unroll
    for (int o = 16; o; o >>= 1) {
        p0 += __shfl_xor_sync(FULLM, p0, o);
        p1 += __shfl_xor_sync(FULLM, p1, o);
        p2 += __shfl_xor_sync(FULLM, p2, o);
    }
    if (lane == 0) {
        out[n * 3 + 0] = p0 + bo[0];
        out[n * 3 + 1] = p1 + bo[1];
        out[n * 3 + 2] = p2 + bo[2];
    }
}

// ---------------------------------------------------------------------------
extern "C" void kernel_launch(void* const* d_in, const int* in_sizes, int n_in,
                              void* d_out, int out_size) {
    const float* x       = (const float*)d_in[0];
    const int*   ei      = (const int*)d_in[1];
    const float* filters = (const float*)d_in[2];
    const float* gamma   = (const float*)d_in[3];
    const float* beta    = (const float*)d_in[4];
    const float* W       = (const float*)d_in[5];
    const float* bo      = (const float*)d_in[6];
    float* out = (float*)d_out;

    cudaFuncSetAttribute(edge_k, cudaFuncAttributeMaxDynamicSharedMemorySize, 65536);

    zero_k<<<512, 256>>>();
    edge_k<<<444, 256, 65536>>>(x, ei, filters);
    node_k<<<(NN * 32 + 255) / 256, 256>>>(x, gamma, beta, W, bo, out);
}

// round 3
// speedup vs baseline: 1.0887x; 1.0887x over previous
#include <cuda_runtime.h>
#include <cstdint>

#define NN 50000
#define NE 400000
#define FULLM 0xffffffffu

// Scratch: per-node accumulator [NN,64] and edge count [NN].
__device__ float g_sum[NN * 64];
__device__ int   g_cnt[NN];

// ---------------------------------------------------------------------------
// Kernel 0: zero scratch (vectorized)
// ---------------------------------------------------------------------------
__global__ void __launch_bounds__(256) zero_k() {
    const int tid = blockIdx.x * blockDim.x + threadIdx.x;
    const int stride = gridDim.x * blockDim.x;
    float4* s4 = (float4*)g_sum;
    const float4 z = {0.f, 0.f, 0.f, 0.f};
    for (int i = tid; i < NN * 16; i += stride) s4[i] = z;
    int4* c4 = (int4*)g_cnt;
    const int4 zi = {0, 0, 0, 0};
    for (int i = tid; i < NN / 4; i += stride) c4[i] = zi;
}

// ---------------------------------------------------------------------------
// Kernel 1: edge kernel.
//   - 64KB filter bank in dynamic SMEM per CTA
//   - lane-per-edge preprocessing, ballot-compacted valid list
//   - DUAL-edge sweep: lanes 0-15 = edge A, lanes 16-31 = edge B,
//     each lane owns 4 output channels (float4 LDS.128)
//   - scatter: 32 lanes issue red.global.add.v4 (two edges per instr wave)
// ---------------------------------------------------------------------------
__global__ void __launch_bounds__(256) edge_k(const float* __restrict__ x,
                                              const int* __restrict__ ei,
                                              const float* __restrict__ filters) {
    extern __shared__ float sf[];  // 16384 floats = 64KB
    for (int i = threadIdx.x; i < 4096; i += blockDim.x)
        ((float4*)sf)[i] = ((const float4*)filters)[i];
    __syncthreads();

    const int lane = threadIdx.x & 31;
    const int gw = (blockIdx.x * blockDim.x + threadIdx.x) >> 5;
    const int nw = (gridDim.x * blockDim.x) >> 5;
    const int* __restrict__ rowp = ei;
    const int* __restrict__ colp = ei + NE;
    const int chOff = (lane & 15) << 2;   // channel group for this lane
    const bool halfA = (lane < 16);

    for (int base = gw * 32; base < NE; base += nw * 32) {
        const int e = base + lane;
        int row = 0;
        float fe0 = 0.f, fe1 = 0.f, fe2 = 0.f, fe3 = 0.f;
        float wcor[8];
        int off[8];
        bool valid = false;

        if (e < NE) {
            row = rowp[e];
            const int col = colp[e];
            atomicAdd(&g_cnt[row], 1);  // count ALL edges (reference semantics)
            const float* xr = x + row * 7;
            const float* xc = x + col * 7;
            fe0 = xc[0]; fe1 = xc[1]; fe2 = xc[2]; fe3 = xc[6];
            const float rx = fe0 - xr[0];
            const float ry = fe1 - xr[1];
            const float rz = fe2 - xr[2];
            const float d2 = rx * rx + ry * ry + rz * rz;
            if (d2 < 0.25f) {
                valid = true;
                const float t = 1.0f - 4.0f * d2;
                const float win = t * t * t;
                const float nrm = sqrtf(d2);
                const float s = tanhf(nrm) / (nrm + 1e-8f);
                // axis reversal: a<-z, b<-y, c<-x
                const float a = (rz * s + 1.0f) * 1.5f;
                const float b = (ry * s + 1.0f) * 1.5f;
                const float c = (rx * s + 1.0f) * 1.5f;
                const float af = floorf(a), bf = floorf(b), cf = floorf(c);
                const int a0 = (int)af, b0 = (int)bf, c0 = (int)cf;
                const float ad = a - af, bd = b - bf, cd = c - cf;
                const int ia[2] = {a0, min(a0 + 1, 3)};
                const int ib[2] = {b0, min(b0 + 1, 3)};
                const int ic[2] = {c0, min(c0 + 1, 3)};
                const float wa[2] = {1.0f - ad, ad};
                const float wb[2] = {1.0f - bd, bd};
                const float wcc[2] = {1.0f - cd, cd};
#pragma unroll
                for (int ka = 0; ka < 2; ka++)
#pragma unroll
                    for (int kb = 0; kb < 2; kb++)
#pragma unroll
                        for (int kc = 0; kc < 2; kc++) {
                            const int k = (ka << 2) | (kb << 1) | kc;
                            off[k] = (((ia[ka] << 2) + ib[kb]) * 4 + ic[kc]) << 8;
                            wcor[k] = win * wa[ka] * wb[kb] * wcc[kc];
                        }
            }
        }

        unsigned vm = __ballot_sync(FULLM, valid);
        while (vm) {
            const int j0 = __ffs(vm) - 1;
            vm &= vm - 1;
            const bool dual = (vm != 0);
            int j1 = j0;
            if (dual) { j1 = __ffs(vm) - 1; vm &= vm - 1; }
            const int src = halfA ? j0 : j1;

            const int rj = __shfl_sync(FULLM, row, src);
            const float e0 = __shfl_sync(FULLM, fe0, src);
            const float e1 = __shfl_sync(FULLM, fe1, src);
            const float e2 = __shfl_sync(FULLM, fe2, src);
            const float e3 = __shfl_sync(FULLM, fe3, src);

            float ax = 0.f, ay = 0.f, az = 0.f, aw = 0.f;
#pragma unroll
            for (int k = 0; k < 8; k++) {
                const float wk = __shfl_sync(FULLM, wcor[k], src);
                const int ok = __shfl_sync(FULLM, off[k], src);
                const float w0 = wk * e0, w1 = wk * e1, w2 = wk * e2, w3 = wk * e3;
                const float* fp = sf + ok + chOff;
                const float4 q0 = *(const float4*)(fp);
                const float4 q1 = *(const float4*)(fp + 64);
                const float4 q2 = *(const float4*)(fp + 128);
                const float4 q3 = *(const float4*)(fp + 192);
                ax += w0 * q0.x + w1 * q1.x + w2 * q2.x + w3 * q3.x;
                ay += w0 * q0.y + w1 * q1.y + w2 * q2.y + w3 * q3.y;
                az += w0 * q0.z + w1 * q1.z + w2 * q2.z + w3 * q3.z;
                aw += w0 * q0.w + w1 * q1.w + w2 * q2.w + w3 * q3.w;
            }
            if (halfA || dual) {
                float* dst = g_sum + (size_t)rj * 64 + chOff;
                asm volatile("red.global.add.v4.f32 [%0], {%1,%2,%3,%4};"
                             :: "l"(dst), "f"(ax), "f"(ay), "f"(az), "f"(aw)
                             : "memory");
            }
        }
    }
}

// ---------------------------------------------------------------------------
// Kernel 2: node epilogue — h=tanh(sum/cnt), concat, layernorm(68), W_out+b.
// One warp per node; lane covers channels {lane, lane+32, lane+64(<4)}.
// ---------------------------------------------------------------------------
__global__ void __launch_bounds__(256) node_k(const float* __restrict__ x,
                                              const float* __restrict__ gamma,
                                              const float* __restrict__ beta,
                                              const float* __restrict__ W,
                                              const float* __restrict__ bo,
                                              float* __restrict__ out) {
    const int lane = threadIdx.x & 31;
    const int n = (blockIdx.x * blockDim.x + threadIdx.x) >> 5;
    if (n >= NN) return;

    const float inv = 1.0f / (float)max(g_cnt[n], 1);
    const float* s = g_sum + (size_t)n * 64;

    float v0, v1, v2 = 0.f;
    if (lane < 4) {
        v0 = (lane < 3) ? x[n * 7 + lane] : x[n * 7 + 6];
        v2 = tanhf(s[lane + 60] * inv);
    } else {
        v0 = tanhf(s[lane - 4] * inv);
    }
    v1 = tanhf(s[lane + 28] * inv);

    float total = v0 + v1 + v2;
#pragma unroll
    for (int o = 16; o; o >>= 1) total += __shfl_xor_sync(FULLM, total, o);
    const float mean = total * (1.0f / 68.0f);

    const float d0 = v0 - mean;
    const float d1 = v1 - mean;
    const float d2v = (lane < 4) ? (v2 - mean) : 0.f;
    float sq = d0 * d0 + d1 * d1 + d2v * d2v;
#pragma unroll
    for (int o = 16; o; o >>= 1) sq += __shfl_xor_sync(FULLM, sq, o);
    const float rstd = rsqrtf(sq * (1.0f / 68.0f) + 1e-5f);

    const int c0 = lane, c1 = lane + 32, c2 = lane + 64;
    const float n0 = d0 * rstd * gamma[c0] + beta[c0];
    const float n1 = d1 * rstd * gamma[c1] + beta[c1];
    float p0 = n0 * W[c0 * 3 + 0] + n1 * W[c1 * 3 + 0];
    float p1 = n0 * W[c0 * 3 + 1] + n1 * W[c1 * 3 + 1];
    float p2 = n0 * W[c0 * 3 + 2] + n1 * W[c1 * 3 + 2];
    if (lane < 4) {
        const float n2 = d2v * rstd * gamma[c2] + beta[c2];
        p0 += n2 * W[c2 * 3 + 0];
        p1 += n2 * W[c2 * 3 + 1];
        p2 += n2 * W[c2 * 3 + 2];
    }
#pragma unroll
    for (int o = 16; o; o >>= 1) {
        p0 += __shfl_xor_sync(FULLM, p0, o);
        p1 += __shfl_xor_sync(FULLM, p1, o);
        p2 += __shfl_xor_sync(FULLM, p2, o);
    }
    if (lane == 0) {
        out[n * 3 + 0] = p0 + bo[0];
        out[n * 3 + 1] = p1 + bo[1];
        out[n * 3 + 2] = p2 + bo[2];
    }
}

// ---------------------------------------------------------------------------
extern "C" void kernel_launch(void* const* d_in, const int* in_sizes, int n_in,
                              void* d_out, int out_size) {
    const float* x       = (const float*)d_in[0];
    const int*   ei      = (const int*)d_in[1];
    const float* filters = (const float*)d_in[2];
    const float* gamma   = (const float*)d_in[3];
    const float* beta    = (const float*)d_in[4];
    const float* W       = (const float*)d_in[5];
    const float* bo      = (const float*)d_in[6];
    float* out = (float*)d_out;

    cudaFuncSetAttribute(edge_k, cudaFuncAttributeMaxDynamicSharedMemorySize, 65536);

    zero_k<<<1024, 256>>>();
    edge_k<<<444, 256, 65536>>>(x, ei, filters);
    node_k<<<(NN * 32 + 255) / 256, 256>>>(x, gamma, beta, W, bo, out);
}

// round 5
// speedup vs baseline: 1.3709x; 1.2593x over previous
#include <cuda_runtime.h>
#include <cuda_fp16.h>
#include <cstdint>

#define NN 50000
#define NE 400000
#define FULLM 0xffffffffu

// Scratch: per-node accumulator [NN,64] and edge count [NN].
// NOTE: device globals are zero-initialized at module load; node_k re-zeroes
// them after consuming, so every kernel_launch call sees zeroed scratch.
__device__ float g_sum[NN * 64];
__device__ int   g_cnt[NN];

// ---------------------------------------------------------------------------
// Kernel 1: edge kernel.
//   - filter bank converted fp32->fp16 into 32KB SMEM per CTA
//     layout: [cell(64)][ipair(2)][chgrp(16)][i_in(2)][c(4)]  (halves)
//     so each lane's 8 in-ch x 4-ch block per corner is one 16B LDS.128
//   - lane-per-edge preprocessing, ballot-compacted valid list
//   - DUAL-edge sweep: lanes 0-15 = edge A, lanes 16-31 = edge B,
//     each lane owns 4 output channels; fp32 accumulation
//   - scatter via red.global.add.v4.f32
// ---------------------------------------------------------------------------
__global__ void __launch_bounds__(256) edge_k(const float* __restrict__ x,
                                              const int* __restrict__ ei,
                                              const float* __restrict__ filters) {
    extern __shared__ __half sf[];  // 16384 halves = 32KB
    // Convert + permute filters into SMEM.
    for (int h2 = threadIdx.x; h2 < 8192; h2 += blockDim.x) {
        const int h = h2 << 1;
        const int cell = h >> 8, rem = h & 255;
        const int ipair = rem >> 7, chgrp = (rem >> 3) & 15;
        const int i_in = (rem >> 2) & 1, c = rem & 3;
        const int i = ipair * 2 + i_in;
        const float2 v = *(const float2*)(filters + cell * 256 + i * 64 + chgrp * 4 + c);
        ((__half2*)sf)[h2] = __floats2half2_rn(v.x, v.y);
    }
    __syncthreads();

    const int lane = threadIdx.x & 31;
    const int gw = (blockIdx.x * blockDim.x + threadIdx.x) >> 5;
    const int nw = (gridDim.x * blockDim.x) >> 5;
    const int* __restrict__ rowp = ei;
    const int* __restrict__ colp = ei + NE;
    const int laneOff = (lane & 15) << 3;   // chgrp*8 halves
    const bool halfA = (lane < 16);

    for (int base = gw * 32; base < NE; base += nw * 32) {
        const int e = base + lane;
        int row = 0;
        float fe0 = 0.f, fe1 = 0.f, fe2 = 0.f, fe3 = 0.f;
        float wcor[8];
        int off[8];
        bool valid = false;

        if (e < NE) {
            row = rowp[e];
            const int col = colp[e];
            atomicAdd(&g_cnt[row], 1);  // count ALL edges (reference semantics)
            const float* xr = x + row * 7;
            const float* xc = x + col * 7;
            fe0 = xc[0]; fe1 = xc[1]; fe2 = xc[2]; fe3 = xc[6];
            const float rx = fe0 - xr[0];
            const float ry = fe1 - xr[1];
            const float rz = fe2 - xr[2];
            const float d2 = rx * rx + ry * ry + rz * rz;
            if (d2 < 0.25f) {
                valid = true;
                const float t = 1.0f - 4.0f * d2;
                const float win = t * t * t;
                const float nrm = sqrtf(d2);
                const float s = tanhf(nrm) / (nrm + 1e-8f);
                // axis reversal: a<-z, b<-y, c<-x
                const float a = (rz * s + 1.0f) * 1.5f;
                const float b = (ry * s + 1.0f) * 1.5f;
                const float c = (rx * s + 1.0f) * 1.5f;
                const float af = floorf(a), bf = floorf(b), cf = floorf(c);
                const int a0 = (int)af, b0 = (int)bf, c0 = (int)cf;
                const float ad = a - af, bd = b - bf, cd = c - cf;
                const int ia[2] = {a0, min(a0 + 1, 3)};
                const int ib[2] = {b0, min(b0 + 1, 3)};
                const int ic[2] = {c0, min(c0 + 1, 3)};
                const float wa[2] = {1.0f - ad, ad};
                const float wb[2] = {1.0f - bd, bd};
                const float wcc[2] = {1.0f - cd, cd};
#pragma unroll
                for (int ka = 0; ka < 2; ka++)
#pragma unroll
                    for (int kb = 0; kb < 2; kb++)
#pragma unroll
                        for (int kc = 0; kc < 2; kc++) {
                            const int k = (ka << 2) | (kb << 1) | kc;
                            // cell index * 256 halves
                            off[k] = ((((ia[ka] << 2) + ib[kb]) << 2) + ic[kc]) << 8;
                            wcor[k] = win * wa[ka] * wb[kb] * wcc[kc];
                        }
            }
        }

        unsigned vm = __ballot_sync(FULLM, valid);
        while (vm) {
            const int j0 = __ffs(vm) - 1;
            vm &= vm - 1;
            const bool dual = (vm != 0);
            int j1 = j0;
            if (dual) { j1 = __ffs(vm) - 1; vm &= vm - 1; }
            const int src = halfA ? j0 : j1;

            const int rj = __shfl_sync(FULLM, row, src);
            const float e0 = __shfl_sync(FULLM, fe0, src);
            const float e1 = __shfl_sync(FULLM, fe1, src);
            const float e2 = __shfl_sync(FULLM, fe2, src);
            const float e3 = __shfl_sync(FULLM, fe3, src);

            float ax = 0.f, ay = 0.f, az = 0.f, aw = 0.f;
#pragma unroll
            for (int k = 0; k < 8; k++) {
                const float wk = __shfl_sync(FULLM, wcor[k], src);
                const int ok = __shfl_sync(FULLM, off[k], src);
                const float w0 = wk * e0, w1 = wk * e1, w2 = wk * e2, w3 = wk * e3;
                const __half* hp = sf + ok + laneOff;
                const uint4 qa = *(const uint4*)(hp);        // i0,i1 x 4ch
                const uint4 qb = *(const uint4*)(hp + 128);  // i2,i3 x 4ch
                float2 u;
                u = __half22float2(*(const __half2*)&qa.x); ax = fmaf(w0, u.x, ax); ay = fmaf(w0, u.y, ay);
                u = __half22float2(*(const __half2*)&qa.y); az = fmaf(w0, u.x, az); aw = fmaf(w0, u.y, aw);
                u = __half22float2(*(const __half2*)&qa.z); ax = fmaf(w1, u.x, ax); ay = fmaf(w1, u.y, ay);
                u = __half22float2(*(const __half2*)&qa.w); az = fmaf(w1, u.x, az); aw = fmaf(w1, u.y, aw);
                u = __half22float2(*(const __half2*)&qb.x); ax = fmaf(w2, u.x, ax); ay = fmaf(w2, u.y, ay);
                u = __half22float2(*(const __half2*)&qb.y); az = fmaf(w2, u.x, az); aw = fmaf(w2, u.y, aw);
                u = __half22float2(*(const __half2*)&qb.z); ax = fmaf(w3, u.x, ax); ay = fmaf(w3, u.y, ay);
                u = __half22float2(*(const __half2*)&qb.w); az = fmaf(w3, u.x, az); aw = fmaf(w3, u.y, aw);
            }
            if (halfA || dual) {
                float* dst = g_sum + (size_t)rj * 64 + ((lane & 15) << 2);
                asm volatile("red.global.add.v4.f32 [%0], {%1,%2,%3,%4};"
                             :: "l"(dst), "f"(ax), "f"(ay), "f"(az), "f"(aw)
                             : "memory");
            }
        }
    }
}

// ---------------------------------------------------------------------------
// Kernel 2: node epilogue — h=tanh(sum/cnt), concat, layernorm(68), W_out+b.
// One warp per node; lane covers channels {lane, lane+32, lane+64(<4)}.
// Also re-zeroes g_sum/g_cnt after consuming (scratch stays clean for the
// next graph replay; zero_k launch eliminated).
// ---------------------------------------------------------------------------
__global__ void __launch_bounds__(256) node_k(const float* __restrict__ x,
                                              const float* __restrict__ gamma,
                                              const float* __restrict__ beta,
                                              const float* __restrict__ W,
                                              const float* __restrict__ bo,
                                              float* __restrict__ out) {
    const int lane = threadIdx.x & 31;
    const int n = (blockIdx.x * blockDim.x + threadIdx.x) >> 5;
    if (n >= NN) return;

    const float inv = 1.0f / (float)max(g_cnt[n], 1);
    float* s = g_sum + (size_t)n * 64;

    float v0, v1, v2 = 0.f;
    if (lane < 4) {
        v0 = (lane < 3) ? x[n * 7 + lane] : x[n * 7 + 6];
        v2 = tanhf(s[lane + 60] * inv);
    } else {
        v0 = tanhf(s[lane - 4] * inv);
    }
    v1 = tanhf(s[lane + 28] * inv);

    // all reads of scratch done -> clean it for the next launch
    __syncwarp();
    ((float2*)s)[lane] = make_float2(0.f, 0.f);
    if (lane == 0) g_cnt[n] = 0;

    float total = v0 + v1 + v2;
#pragma unroll
    for (int o = 16; o; o >>= 1) total += __shfl_xor_sync(FULLM, total, o);
    const float mean = total * (1.0f / 68.0f);

    const float d0 = v0 - mean;
    const float d1 = v1 - mean;
    const float d2v = (lane < 4) ? (v2 - mean) : 0.f;
    float sq = d0 * d0 + d1 * d1 + d2v * d2v;
#pragma unroll
    for (int o = 16; o; o >>= 1) sq += __shfl_xor_sync(FULLM, sq, o);
    const float rstd = rsqrtf(sq * (1.0f / 68.0f) + 1e-5f);

    const int c0 = lane, c1 = lane + 32, c2 = lane + 64;
    const float n0 = d0 * rstd * gamma[c0] + beta[c0];
    const float n1 = d1 * rstd * gamma[c1] + beta[c1];
    float p0 = n0 * W[c0 * 3 + 0] + n1 * W[c1 * 3 + 0];
    float p1 = n0 * W[c0 * 3 + 1] + n1 * W[c1 * 3 + 1];
    float p2 = n0 * W[c0 * 3 + 2] + n1 * W[c1 * 3 + 2];
    if (lane < 4) {
        const float n2 = d2v * rstd * gamma[c2] + beta[c2];
        p0 += n2 * W[c2 * 3 + 0];
        p1 += n2 * W[c2 * 3 + 1];
        p2 += n2 * W[c2 * 3 + 2];
    }
#pragma unroll
    for (int o = 16; o; o >>= 1) {
        p0 += __shfl_xor_sync(FULLM, p0, o);
        p1 += __shfl_xor_sync(FULLM, p1, o);
        p2 += __shfl_xor_sync(FULLM, p2, o);
    }
    if (lane == 0) {
        out[n * 3 + 0] = p0 + bo[0];
        out[n * 3 + 1] = p1 + bo[1];
        out[n * 3 + 2] = p2 + bo[2];
    }
}

// ---------------------------------------------------------------------------
extern "C" void kernel_launch(void* const* d_in, const int* in_sizes, int n_in,
                              void* d_out, int out_size) {
    const float* x       = (const float*)d_in[0];
    const int*   ei      = (const int*)d_in[1];
    const float* filters = (const float*)d_in[2];
    const float* gamma   = (const float*)d_in[3];
    const float* beta    = (const float*)d_in[4];
    const float* W       = (const float*)d_in[5];
    const float* bo      = (const float*)d_in[6];
    float* out = (float*)d_out;

    edge_k<<<444, 256, 32768>>>(x, ei, filters);
    node_k<<<(NN * 32 + 255) / 256, 256>>>(x, gamma, beta, W, bo, out);
}

// round 6
// speedup vs baseline: 1.4642x; 1.0680x over previous
#include <cuda_runtime.h>
#include <cuda_fp16.h>
#include <cstdint>

#define NN 50000
#define NE 400000
#define FULLM 0xffffffffu

// Scratch: per-node accumulator [NN,64] and edge count [NN].
// Device globals are zero-initialized at module load; node_k re-zeroes them
// after consuming, so every kernel_launch/graph replay sees zeroed scratch.
__device__ float g_sum[NN * 64];
__device__ int   g_cnt[NN];

// ---------------------------------------------------------------------------
// Kernel 1: edge kernel.
//   - filter bank converted fp32->fp16 into 32KB SMEM per CTA
//     layout: [cell(64)][ipair(2)][chgrp(16)][i_in(2)][c(4)]  (halves)
//   - lane-per-edge preprocessing, ballot-compacted valid list
//   - DUAL-edge sweep: lanes 0-15 = edge A, lanes 16-31 = edge B,
//     each lane owns 4 output channels; fp32 accumulation
//   - scatter via red.global.add.v4.f32
// ---------------------------------------------------------------------------
__global__ void __launch_bounds__(256) edge_k(const float* __restrict__ x,
                                              const int* __restrict__ ei,
                                              const float* __restrict__ filters) {
    extern __shared__ __half sf[];  // 16384 halves = 32KB
    for (int h2 = threadIdx.x; h2 < 8192; h2 += blockDim.x) {
        const int h = h2 << 1;
        const int cell = h >> 8, rem = h & 255;
        const int ipair = rem >> 7, chgrp = (rem >> 3) & 15;
        const int i_in = (rem >> 2) & 1, c = rem & 3;
        const int i = ipair * 2 + i_in;
        const float2 v = *(const float2*)(filters + cell * 256 + i * 64 + chgrp * 4 + c);
        ((__half2*)sf)[h2] = __floats2half2_rn(v.x, v.y);
    }
    __syncthreads();

    const int lane = threadIdx.x & 31;
    const int gw = (blockIdx.x * blockDim.x + threadIdx.x) >> 5;
    const int nw = (gridDim.x * blockDim.x) >> 5;
    const int* __restrict__ rowp = ei;
    const int* __restrict__ colp = ei + NE;
    const int laneOff = (lane & 15) << 3;   // chgrp*8 halves
    const bool halfA = (lane < 16);

    for (int base = gw * 32; base < NE; base += nw * 32) {
        const int e = base + lane;
        int row = 0;
        float fe0 = 0.f, fe1 = 0.f, fe2 = 0.f, fe3 = 0.f;
        float wcor[8];
        int off[8];
        bool valid = false;

        if (e < NE) {
            row = rowp[e];
            const int col = colp[e];
            atomicAdd(&g_cnt[row], 1);  // count ALL edges (reference semantics)
            const float* xr = x + row * 7;
            const float* xc = x + col * 7;
            fe0 = xc[0]; fe1 = xc[1]; fe2 = xc[2]; fe3 = xc[6];
            const float rx = fe0 - xr[0];
            const float ry = fe1 - xr[1];
            const float rz = fe2 - xr[2];
            const float d2 = rx * rx + ry * ry + rz * rz;
            if (d2 < 0.25f) {
                valid = true;
                const float t = 1.0f - 4.0f * d2;
                const float win = t * t * t;
                const float nrm = sqrtf(d2);
                const float s = tanhf(nrm) / (nrm + 1e-8f);
                // axis reversal: a<-z, b<-y, c<-x
                const float a = (rz * s + 1.0f) * 1.5f;
                const float b = (ry * s + 1.0f) * 1.5f;
                const float c = (rx * s + 1.0f) * 1.5f;
                const float af = floorf(a), bf = floorf(b), cf = floorf(c);
                const int a0 = (int)af, b0 = (int)bf, c0 = (int)cf;
                const float ad = a - af, bd = b - bf, cd = c - cf;
                const int ia[2] = {a0, min(a0 + 1, 3)};
                const int ib[2] = {b0, min(b0 + 1, 3)};
                const int ic[2] = {c0, min(c0 + 1, 3)};
                const float wa[2] = {1.0f - ad, ad};
                const float wb[2] = {1.0f - bd, bd};
                const float wcc[2] = {1.0f - cd, cd};
#pragma unroll
                for (int ka = 0; ka < 2; ka++)
#pragma unroll
                    for (int kb = 0; kb < 2; kb++)
#pragma unroll
                        for (int kc = 0; kc < 2; kc++) {
                            const int k = (ka << 2) | (kb << 1) | kc;
                            off[k] = ((((ia[ka] << 2) + ib[kb]) << 2) + ic[kc]) << 8;
                            wcor[k] = win * wa[ka] * wb[kb] * wcc[kc];
                        }
            }
        }

        unsigned vm = __ballot_sync(FULLM, valid);
        while (vm) {
            const int j0 = __ffs(vm) - 1;
            vm &= vm - 1;
            const bool dual = (vm != 0);
            int j1 = j0;
            if (dual) { j1 = __ffs(vm) - 1; vm &= vm - 1; }
            const int src = halfA ? j0 : j1;

            const int rj = __shfl_sync(FULLM, row, src);
            const float e0 = __shfl_sync(FULLM, fe0, src);
            const float e1 = __shfl_sync(FULLM, fe1, src);
            const float e2 = __shfl_sync(FULLM, fe2, src);
            const float e3 = __shfl_sync(FULLM, fe3, src);

            float ax = 0.f, ay = 0.f, az = 0.f, aw = 0.f;
#pragma unroll
            for (int k = 0; k < 8; k++) {
                const float wk = __shfl_sync(FULLM, wcor[k], src);
                const int ok = __shfl_sync(FULLM, off[k], src);
                const float w0 = wk * e0, w1 = wk * e1, w2 = wk * e2, w3 = wk * e3;
                const __half* hp = sf + ok + laneOff;
                const uint4 qa = *(const uint4*)(hp);        // i0,i1 x 4ch
                const uint4 qb = *(const uint4*)(hp + 128);  // i2,i3 x 4ch
                float2 u;
                u = __half22float2(*(const __half2*)&qa.x); ax = fmaf(w0, u.x, ax); ay = fmaf(w0, u.y, ay);
                u = __half22float2(*(const __half2*)&qa.y); az = fmaf(w0, u.x, az); aw = fmaf(w0, u.y, aw);
                u = __half22float2(*(const __half2*)&qa.z); ax = fmaf(w1, u.x, ax); ay = fmaf(w1, u.y, ay);
                u = __half22float2(*(const __half2*)&qa.w); az = fmaf(w1, u.x, az); aw = fmaf(w1, u.y, aw);
                u = __half22float2(*(const __half2*)&qb.x); ax = fmaf(w2, u.x, ax); ay = fmaf(w2, u.y, ay);
                u = __half22float2(*(const __half2*)&qb.y); az = fmaf(w2, u.x, az); aw = fmaf(w2, u.y, aw);
                u = __half22float2(*(const __half2*)&qb.z); ax = fmaf(w3, u.x, ax); ay = fmaf(w3, u.y, ay);
                u = __half22float2(*(const __half2*)&qb.w); az = fmaf(w3, u.x, az); aw = fmaf(w3, u.y, aw);
            }
            if (halfA || dual) {
                float* dst = g_sum + (size_t)rj * 64 + ((lane & 15) << 2);
                asm volatile("red.global.add.v4.f32 [%0], {%1,%2,%3,%4};"
                             :: "l"(dst), "f"(ax), "f"(ay), "f"(az), "f"(aw)
                             : "memory");
            }
        }
    }
}

// ---------------------------------------------------------------------------
// Kernel 2: node epilogue. TWO nodes per warp (16-lane halves).
// Lane k (0-15 within half) owns conv channels 4k..4k+3 (one float4);
// lanes k<4 also own enc channel k. 4-level xor-shuffle reductions stay
// inside the 16-lane half automatically (offsets 8,4,2,1).
// Also re-zeroes g_sum/g_cnt after consuming.
// ---------------------------------------------------------------------------
__global__ void __launch_bounds__(256) node_k(const float* __restrict__ x,
                                              const float* __restrict__ gamma,
                                              const float* __restrict__ beta,
                                              const float* __restrict__ W,
                                              const float* __restrict__ bo,
                                              float* __restrict__ out) {
    const int lane = threadIdx.x & 31;
    const int half = lane >> 4;
    const int k = lane & 15;
    const int n = ((blockIdx.x * blockDim.x + threadIdx.x) >> 5) * 2 + half;
    if (n >= NN) return;

    float* s = g_sum + (size_t)n * 64;
    const float inv = 1.0f / (float)max(g_cnt[n], 1);

    const float4 hv = ((const float4*)s)[k];
    const float h0 = tanhf(hv.x * inv);
    const float h1 = tanhf(hv.y * inv);
    const float h2 = tanhf(hv.z * inv);
    const float h3 = tanhf(hv.w * inv);
    float ev = 0.f;
    if (k < 4) ev = (k < 3) ? x[n * 7 + k] : x[n * 7 + 6];

    // scratch consumed -> clean it for the next graph replay
    __syncwarp();
    ((float4*)s)[k] = make_float4(0.f, 0.f, 0.f, 0.f);
    if (k == 0) g_cnt[n] = 0;

    float total = h0 + h1 + h2 + h3 + ev;
#pragma unroll
    for (int o = 8; o; o >>= 1) total += __shfl_xor_sync(FULLM, total, o);
    const float mean = total * (1.0f / 68.0f);

    const float d0 = h0 - mean, d1 = h1 - mean, d2 = h2 - mean, d3 = h3 - mean;
    const float de = (k < 4) ? (ev - mean) : 0.f;
    float sq = d0 * d0 + d1 * d1 + d2 * d2 + d3 * d3 + de * de;
#pragma unroll
    for (int o = 8; o; o >>= 1) sq += __shfl_xor_sync(FULLM, sq, o);
    const float rstd = rsqrtf(sq * (1.0f / 68.0f) + 1e-5f);

    // conv channels: cat idx 4+4k .. 4+4k+3
    const float4 g4 = ((const float4*)(gamma + 4))[k];
    const float4 b4 = ((const float4*)(beta + 4))[k];
    const float n0 = d0 * rstd * g4.x + b4.x;
    const float n1 = d1 * rstd * g4.y + b4.y;
    const float n2 = d2 * rstd * g4.z + b4.z;
    const float n3 = d3 * rstd * g4.w + b4.w;

    // W rows 4+4k..4+4k+3 = 12 consecutive floats at W+12+12k (16B aligned)
    const float4* Wp = (const float4*)(W + 12) + 3 * k;
    const float4 w0 = Wp[0], w1 = Wp[1], w2 = Wp[2];
    float p0 = n0 * w0.x + n1 * w0.w + n2 * w1.z + n3 * w2.y;
    float p1 = n0 * w0.y + n1 * w1.x + n2 * w1.w + n3 * w2.z;
    float p2 = n0 * w0.z + n1 * w1.y + n2 * w2.x + n3 * w2.w;
    if (k < 4) {
        const float ne = de * rstd * gamma[k] + beta[k];
        p0 += ne * W[3 * k + 0];
        p1 += ne * W[3 * k + 1];
        p2 += ne * W[3 * k + 2];
    }
#pragma unroll
    for (int o = 8; o; o >>= 1) {
        p0 += __shfl_xor_sync(FULLM, p0, o);
        p1 += __shfl_xor_sync(FULLM, p1, o);
        p2 += __shfl_xor_sync(FULLM, p2, o);
    }
    if (k == 0) {
        out[n * 3 + 0] = p0 + bo[0];
        out[n * 3 + 1] = p1 + bo[1];
        out[n * 3 + 2] = p2 + bo[2];
    }
}

// ---------------------------------------------------------------------------
extern "C" void kernel_launch(void* const* d_in, const int* in_sizes, int n_in,
                              void* d_out, int out_size) {
    const float* x       = (const float*)d_in[0];
    const int*   ei      = (const int*)d_in[1];
    const float* filters = (const float*)d_in[2];
    const float* gamma   = (const float*)d_in[3];
    const float* beta    = (const float*)d_in[4];
    const float* W       = (const float*)d_in[5];
    const float* bo      = (const float*)d_in[6];
    float* out = (float*)d_out;

    edge_k<<<888, 256, 32768>>>(x, ei, filters);
    node_k<<<3125, 256>>>(x, gamma, beta, W, bo, out);  // 2 nodes/warp
}

// round 7
// speedup vs baseline: 1.4751x; 1.0075x over previous
#include <cuda_runtime.h>
#include <cuda_fp16.h>
#include <cstdint>

#define NN 50000
#define NE 400000
#define FULLM 0xffffffffu

// Scratch: per-node accumulator [NN,64] and edge count [NN].
// Device globals are zero-initialized at module load; node_k re-zeroes them
// after consuming, so every kernel_launch/graph replay sees zeroed scratch.
__device__ float g_sum[NN * 64];
__device__ int   g_cnt[NN];

// ---- packed f32x2 helpers (sm_100a) ---------------------------------------
#define PACK2(d, lo, hi) \
    asm("mov.b64 %0, {%1, %2};" : "=l"(d) : "f"(lo), "f"(hi))
#define UNPACK2(lo, hi, v) \
    asm("mov.b64 {%0, %1}, %2;" : "=f"(lo), "=f"(hi) : "l"(v))
#define FMA2(d, a, b, c) \
    asm("fma.rn.f32x2 %0, %1, %2, %3;" : "=l"(d) : "l"(a), "l"(b), "l"(c))
// f16x2 (as u32) -> f32x2 (as u64)
#define CVT2(d, s) \
    asm("{\n\t.reg .b16 l,h;\n\t.reg .f32 fl,fh;\n\t" \
        "mov.b32 {l,h}, %1;\n\t" \
        "cvt.f32.f16 fl, l;\n\tcvt.f32.f16 fh, h;\n\t" \
        "mov.b64 %0, {fl,fh};\n\t}" : "=l"(d) : "r"(s))

__device__ __forceinline__ float tanh_fast(float v) {
    float y;
    asm("tanh.approx.f32 %0, %1;" : "=f"(y) : "f"(v));
    return y;
}

// ---------------------------------------------------------------------------
// Kernel 1: edge kernel.
//   - filter bank fp32->fp16 in 32KB SMEM per CTA
//     layout: [cell(64)][ipair(2)][chgrp(16)][i_in(2)][c(4)]  (halves)
//   - lane-per-edge preprocessing, ballot-compacted valid list
//   - DUAL-edge sweep: lanes 0-15 = edge A, lanes 16-31 = edge B
//   - corner loop accumulates A_i[c] = sum_k w_k F_k[i][c] in 8 f32x2 regs
//     (FFMA2); e-vector combine hoisted to once per edge
//   - scatter via red.global.add.v4.f32
// ---------------------------------------------------------------------------
__global__ void __launch_bounds__(256) edge_k(const float* __restrict__ x,
                                              const int* __restrict__ ei,
                                              const float* __restrict__ filters) {
    extern __shared__ __half sf[];  // 16384 halves = 32KB
    for (int h2 = threadIdx.x; h2 < 8192; h2 += blockDim.x) {
        const int h = h2 << 1;
        const int cell = h >> 8, rem = h & 255;
        const int ipair = rem >> 7, chgrp = (rem >> 3) & 15;
        const int i_in = (rem >> 2) & 1, c = rem & 3;
        const int i = ipair * 2 + i_in;
        const float2 v = *(const float2*)(filters + cell * 256 + i * 64 + chgrp * 4 + c);
        ((__half2*)sf)[h2] = __floats2half2_rn(v.x, v.y);
    }
    __syncthreads();

    const int lane = threadIdx.x & 31;
    const int gw = (blockIdx.x * blockDim.x + threadIdx.x) >> 5;
    const int nw = (gridDim.x * blockDim.x) >> 5;
    const int* __restrict__ rowp = ei;
    const int* __restrict__ colp = ei + NE;
    const int laneOff = (lane & 15) << 3;   // chgrp*8 halves
    const bool halfA = (lane < 16);

    for (int base = gw * 32; base < NE; base += nw * 32) {
        const int e = base + lane;
        int row = 0;
        float fe0 = 0.f, fe1 = 0.f, fe2 = 0.f, fe3 = 0.f;
        float wcor[8];
        int off[8];
        bool valid = false;

        if (e < NE) {
            row = rowp[e];
            const int col = colp[e];
            atomicAdd(&g_cnt[row], 1);  // count ALL edges (reference semantics)
            const float* xr = x + row * 7;
            const float* xc = x + col * 7;
            fe0 = xc[0]; fe1 = xc[1]; fe2 = xc[2]; fe3 = xc[6];
            const float rx = fe0 - xr[0];
            const float ry = fe1 - xr[1];
            const float rz = fe2 - xr[2];
            const float d2 = rx * rx + ry * ry + rz * rz;
            if (d2 < 0.25f) {
                valid = true;
                const float t = 1.0f - 4.0f * d2;
                const float win = t * t * t;
                const float nrm = sqrtf(d2);
                const float s = tanhf(nrm) / (nrm + 1e-8f);
                // axis reversal: a<-z, b<-y, c<-x
                const float a = (rz * s + 1.0f) * 1.5f;
                const float b = (ry * s + 1.0f) * 1.5f;
                const float c = (rx * s + 1.0f) * 1.5f;
                const float af = floorf(a), bf = floorf(b), cf = floorf(c);
                const int a0 = (int)af, b0 = (int)bf, c0 = (int)cf;
                const float ad = a - af, bd = b - bf, cd = c - cf;
                const int ia[2] = {a0, min(a0 + 1, 3)};
                const int ib[2] = {b0, min(b0 + 1, 3)};
                const int ic[2] = {c0, min(c0 + 1, 3)};
                const float wa[2] = {1.0f - ad, ad};
                const float wb[2] = {1.0f - bd, bd};
                const float wcc[2] = {1.0f - cd, cd};
#pragma unroll
                for (int ka = 0; ka < 2; ka++)
#pragma unroll
                    for (int kb = 0; kb < 2; kb++)
#pragma unroll
                        for (int kc = 0; kc < 2; kc++) {
                            const int k = (ka << 2) | (kb << 1) | kc;
                            off[k] = ((((ia[ka] << 2) + ib[kb]) << 2) + ic[kc]) << 8;
                            wcor[k] = win * wa[ka] * wb[kb] * wcc[kc];
                        }
            }
        }

        unsigned vm = __ballot_sync(FULLM, valid);
        while (vm) {
            const int j0 = __ffs(vm) - 1;
            vm &= vm - 1;
            const bool dual = (vm != 0);
            int j1 = j0;
            if (dual) { j1 = __ffs(vm) - 1; vm &= vm - 1; }
            const int src = halfA ? j0 : j1;

            const int rj = __shfl_sync(FULLM, row, src);
            const float e0 = __shfl_sync(FULLM, fe0, src);
            const float e1 = __shfl_sync(FULLM, fe1, src);
            const float e2 = __shfl_sync(FULLM, fe2, src);
            const float e3 = __shfl_sync(FULLM, fe3, src);

            // A[2*i+p]: in-channel i, channel-pair p (p=0 -> c0c1, p=1 -> c2c3)
            uint64_t A0 = 0ull, A1 = 0ull, A2 = 0ull, A3 = 0ull;
            uint64_t A4 = 0ull, A5 = 0ull, A6 = 0ull, A7 = 0ull;
#pragma unroll
            for (int k = 0; k < 8; k++) {
                const float wk = __shfl_sync(FULLM, wcor[k], src);
                const int ok = __shfl_sync(FULLM, off[k], src);
                uint64_t wk2; PACK2(wk2, wk, wk);
                const __half* hp = sf + ok + laneOff;
                const uint4 qa = *(const uint4*)(hp);        // i0,i1 x (c01,c23)
                const uint4 qb = *(const uint4*)(hp + 128);  // i2,i3 x (c01,c23)
                uint64_t f;
                CVT2(f, qa.x); FMA2(A0, wk2, f, A0);
                CVT2(f, qa.y); FMA2(A1, wk2, f, A1);
                CVT2(f, qa.z); FMA2(A2, wk2, f, A2);
                CVT2(f, qa.w); FMA2(A3, wk2, f, A3);
                CVT2(f, qb.x); FMA2(A4, wk2, f, A4);
                CVT2(f, qb.y); FMA2(A5, wk2, f, A5);
                CVT2(f, qb.z); FMA2(A6, wk2, f, A6);
                CVT2(f, qb.w); FMA2(A7, wk2, f, A7);
            }
            // combine with e-vector: acc[c] = sum_i e_i * A_i[c]
            uint64_t ev, acc01 = 0ull, acc23 = 0ull;
            PACK2(ev, e0, e0); FMA2(acc01, ev, A0, acc01); FMA2(acc23, ev, A1, acc23);
            PACK2(ev, e1, e1); FMA2(acc01, ev, A2, acc01); FMA2(acc23, ev, A3, acc23);
            PACK2(ev, e2, e2); FMA2(acc01, ev, A4, acc01); FMA2(acc23, ev, A5, acc23);
            PACK2(ev, e3, e3); FMA2(acc01, ev, A6, acc01); FMA2(acc23, ev, A7, acc23);
            float ax, ay, az, aw;
            UNPACK2(ax, ay, acc01);
            UNPACK2(az, aw, acc23);

            if (halfA || dual) {
                float* dst = g_sum + (size_t)rj * 64 + ((lane & 15) << 2);
                asm volatile("red.global.add.v4.f32 [%0], {%1,%2,%3,%4};"
                             :: "l"(dst), "f"(ax), "f"(ay), "f"(az), "f"(aw)
                             : "memory");
            }
        }
    }
}

// ---------------------------------------------------------------------------
// Kernel 2: node epilogue. TWO nodes per warp (16-lane halves).
// Lane k (0-15 within half) owns conv channels 4k..4k+3 (one float4);
// lanes k<4 also own enc channel k. tanh via MUFU tanh.approx.
// Also re-zeroes g_sum/g_cnt after consuming.
// ---------------------------------------------------------------------------
__global__ void __launch_bounds__(256) node_k(const float* __restrict__ x,
                                              const float* __restrict__ gamma,
                                              const float* __restrict__ beta,
                                              const float* __restrict__ W,
                                              const float* __restrict__ bo,
                                              float* __restrict__ out) {
    const int lane = threadIdx.x & 31;
    const int half = lane >> 4;
    const int k = lane & 15;
    const int n = ((blockIdx.x * blockDim.x + threadIdx.x) >> 5) * 2 + half;
    if (n >= NN) return;

    float* s = g_sum + (size_t)n * 64;
    const float inv = 1.0f / (float)max(g_cnt[n], 1);

    const float4 hv = ((const float4*)s)[k];
    const float h0 = tanh_fast(hv.x * inv);
    const float h1 = tanh_fast(hv.y * inv);
    const float h2 = tanh_fast(hv.z * inv);
    const float h3 = tanh_fast(hv.w * inv);
    float ev = 0.f;
    if (k < 4) ev = (k < 3) ? x[n * 7 + k] : x[n * 7 + 6];

    // scratch consumed -> clean it for the next graph replay
    __syncwarp();
    ((float4*)s)[k] = make_float4(0.f, 0.f, 0.f, 0.f);
    if (k == 0) g_cnt[n] = 0;

    float total = h0 + h1 + h2 + h3 + ev;
#pragma unroll
    for (int o = 8; o; o >>= 1) total += __shfl_xor_sync(FULLM, total, o);
    const float mean = total * (1.0f / 68.0f);

    const float d0 = h0 - mean, d1 = h1 - mean, d2 = h2 - mean, d3 = h3 - mean;
    const float de = (k < 4) ? (ev - mean) : 0.f;
    float sq = d0 * d0 + d1 * d1 + d2 * d2 + d3 * d3 + de * de;
#pragma unroll
    for (int o = 8; o; o >>= 1) sq += __shfl_xor_sync(FULLM, sq, o);
    const float rstd = rsqrtf(sq * (1.0f / 68.0f) + 1e-5f);

    // conv channels: cat idx 4+4k .. 4+4k+3
    const float4 g4 = ((const float4*)(gamma + 4))[k];
    const float4 b4 = ((const float4*)(beta + 4))[k];
    const float n0 = d0 * rstd * g4.x + b4.x;
    const float n1 = d1 * rstd * g4.y + b4.y;
    const float n2 = d2 * rstd * g4.z + b4.z;
    const float n3 = d3 * rstd * g4.w + b4.w;

    // W rows 4+4k..4+4k+3 = 12 consecutive floats at W+12+12k (16B aligned)
    const float4* Wp = (const float4*)(W + 12) + 3 * k;
    const float4 w0 = Wp[0], w1 = Wp[1], w2 = Wp[2];
    float p0 = n0 * w0.x + n1 * w0.w + n2 * w1.z + n3 * w2.y;
    float p1 = n0 * w0.y + n1 * w1.x + n2 * w1.w + n3 * w2.z;
    float p2 = n0 * w0.z + n1 * w1.y + n2 * w2.x + n3 * w2.w;
    if (k < 4) {
        const float ne = de * rstd * gamma[k] + beta[k];
        p0 += ne * W[3 * k + 0];
        p1 += ne * W[3 * k + 1];
        p2 += ne * W[3 * k + 2];
    }
#pragma unroll
    for (int o = 8; o; o >>= 1) {
        p0 += __shfl_xor_sync(FULLM, p0, o);
        p1 += __shfl_xor_sync(FULLM, p1, o);
        p2 += __shfl_xor_sync(FULLM, p2, o);
    }
    if (k == 0) {
        out[n * 3 + 0] = p0 + bo[0];
        out[n * 3 + 1] = p1 + bo[1];
        out[n * 3 + 2] = p2 + bo[2];
    }
}

// ---------------------------------------------------------------------------
extern "C" void kernel_launch(void* const* d_in, const int* in_sizes, int n_in,
                              void* d_out, int out_size) {
    const float* x       = (const float*)d_in[0];
    const int*   ei      = (const int*)d_in[1];
    const float* filters = (const float*)d_in[2];
    const float* gamma   = (const float*)d_in[3];
    const float* beta    = (const float*)d_in[4];
    const float* W       = (const float*)d_in[5];
    const float* bo      = (const float*)d_in[6];
    float* out = (float*)d_out;

    edge_k<<<888, 256, 32768>>>(x, ei, filters);
    node_k<<<3125, 256>>>(x, gamma, beta, W, bo, out);  // 2 nodes/warp
}